// round 16
// baseline (speedup 1.0000x reference)
#include <cuda_runtime.h>
#include <cstdint>

#define NN_MAX 50000
#define EE_MAX 400000

// ---------------- scratch (device globals; no allocs allowed) ----------------
__device__ float g_bc[512];                   // bn | 0 | 0 | bv
__device__ float4 g_MeFrag[8 * 16 * 32];      // Me fragments (hi0,hi1,lo0,lo1)
__device__ float4 g_WcFrag[16 * 64 * 32];     // Wcomb fragments (hi0,hi1,lo0,lo1), 512KB
__device__ float g_c1[128];                   // bq@A1q + bk@A1k + be@A1e + b1
__device__ float g_Q[NN_MAX * 128];
__device__ float g_Kf[NN_MAX * 128];
__device__ float g_V[NN_MAX * 128];
__device__ float g_s[EE_MAX];
__device__ float g_pmax[512];
__device__ float g_psum[512];
__device__ float g_red[2];                    // gmax, 1/gsum
__device__ float g_acc[NN_MAX * 128];         // H written by node_gemm; scatter adds; ln reads

__device__ __forceinline__ float lrelu(float x) { return x > 0.f ? x : 0.2f * x; }

__device__ __forceinline__ uint32_t f2tf32(float x) {
    uint32_t r; asm("cvt.rna.tf32.f32 %0, %1;" : "=r"(r) : "f"(x)); return r;
}

__device__ __forceinline__ void mma_tf32(float c[4], const uint32_t a[4],
                                         uint32_t b0, uint32_t b1) {
    asm volatile(
        "mma.sync.aligned.m16n8k8.row.col.f32.tf32.tf32.f32 "
        "{%0,%1,%2,%3}, {%4,%5,%6,%7}, {%8,%9}, {%0,%1,%2,%3};"
        : "+f"(c[0]), "+f"(c[1]), "+f"(c[2]), "+f"(c[3])
        : "r"(a[0]), "r"(a[1]), "r"(a[2]), "r"(a[3]), "r"(b0), "r"(b1));
}

// ---------------- prep: fold weights into fragment layouts ----------------
__global__ void prep_kernel(const float* __restrict__ Wn, const float* __restrict__ Wq,
                            const float* __restrict__ Wk, const float* __restrict__ Wv,
                            const float* __restrict__ We, const float* __restrict__ A1,
                            const float* __restrict__ b1, const float* __restrict__ bq,
                            const float* __restrict__ bk, const float* __restrict__ be,
                            const float* __restrict__ bn, const float* __restrict__ bv) {
    int t = blockIdx.x * 256 + threadIdx.x;
    if (t < 4096) {
        int i = t;
        int kt = i >> 9, nt = (i >> 5) & 15, lane = i & 31;
        int g = lane >> 2, t4 = lane & 3;
        int k1 = kt * 8 + t4, k2 = k1 + 4;
        int n = nt * 8 + g;
        float s1 = 0.f, s2 = 0.f;
        #pragma unroll 8
        for (int u = 0; u < 128; u++) {
            float a = A1[(256 + u) * 128 + n];
            s1 += We[k1 * 128 + u] * a;
            s2 += We[k2 * 128 + u] * a;
        }
        float h1 = __uint_as_float(f2tf32(s1));
        float h2 = __uint_as_float(f2tf32(s2));
        float l1 = __uint_as_float(f2tf32(s1 - h1));
        float l2 = __uint_as_float(f2tf32(s2 - h2));
        g_MeFrag[i] = make_float4(h1, h2, l1, l2);
    } else if (t < 4096 + 32768) {
        int i = t - 4096;
        int kt = i >> 11, nt = (i >> 5) & 63, lane = i & 31;
        int g = lane >> 2, t4 = lane & 3;
        int k1 = kt * 8 + t4, k2 = k1 + 4;
        int n = nt * 8 + g;
        float s1, s2;
        if (n < 128) {
            s1 = Wn[k1 * 128 + n];
            s2 = Wn[k2 * 128 + n];
        } else if (n < 256) {
            int j = n - 128;
            s1 = 0.f; s2 = 0.f;
            #pragma unroll 8
            for (int u = 0; u < 128; u++) {
                float a = A1[u * 128 + j];
                s1 += Wq[k1 * 128 + u] * a;
                s2 += Wq[k2 * 128 + u] * a;
            }
        } else if (n < 384) {
            int j = n - 256;
            s1 = 0.f; s2 = 0.f;
            #pragma unroll 8
            for (int u = 0; u < 128; u++) {
                float a = A1[(128 + u) * 128 + j];
                s1 += Wk[k1 * 128 + u] * a;
                s2 += Wk[k2 * 128 + u] * a;
            }
        } else {
            int j = n - 384;
            s1 = Wv[k1 * 128 + j];
            s2 = Wv[k2 * 128 + j];
        }
        float h1 = __uint_as_float(f2tf32(s1));
        float h2 = __uint_as_float(f2tf32(s2));
        float l1 = __uint_as_float(f2tf32(s1 - h1));
        float l2 = __uint_as_float(f2tf32(s2 - h2));
        g_WcFrag[(kt * 64 + nt) * 32 + lane] = make_float4(h1, h2, l1, l2);
    } else if (t < 4096 + 32768 + 128) {
        int j = t - (4096 + 32768);
        float s = b1[j];
        for (int u = 0; u < 128; u++) {
            s += bq[u] * A1[u * 128 + j];
            s += bk[u] * A1[(128 + u) * 128 + j];
            s += be[u] * A1[(256 + u) * 128 + j];
        }
        g_c1[j] = s;
    } else if (t < 4096 + 32768 + 128 + 512) {
        int j = t - (4096 + 32768 + 128);
        g_bc[j] = (j < 128) ? bn[j] : (j >= 384 ? bv[j - 384] : 0.f);
    }
}

// ---------------- node GEMM (tf32 mma): C[M,512] = A @ Wcomb + bc ----------------
// One block per 128-row stripe; loops over all 4 column groups reusing the
// staged A tile (A traffic / staging barriers divided by 4 vs per-group blocks).
// grp 0 (H) goes directly into g_acc (scatter accumulates on top; ln reads g_acc).
#define NSM_FLOATS (128 * 132)
#define NSM_BYTES  (NSM_FLOATS * 4)

__global__ void __launch_bounds__(256) node_gemm_kernel(const float* __restrict__ A, int M) {
    extern __shared__ float smem[];
    int tid = threadIdx.x;
    int rowBase = blockIdx.x * 128;

    #pragma unroll
    for (int i = 0; i < 16; i++) {
        int s = tid + i * 256;
        int r = s >> 5, c4 = s & 31;
        int row = rowBase + r;
        float4 v = make_float4(0.f, 0.f, 0.f, 0.f);
        if (row < M) v = *reinterpret_cast<const float4*>(&A[row * 128 + c4 * 4]);
        *reinterpret_cast<float4*>(&smem[r * 132 + c4 * 4]) = v;
    }
    __syncthreads();

    int w = tid >> 5, lane = tid & 31;
    int g = lane >> 2, t4 = lane & 3;
    int m0 = w * 16;
    int r0 = rowBase + m0 + g, r1 = r0 + 8;

    #pragma unroll 1
    for (int grp = 0; grp < 4; grp++) {
        float c[16][4];
        #pragma unroll
        for (int nt = 0; nt < 16; nt++)
            #pragma unroll
            for (int j = 0; j < 4; j++) c[nt][j] = 0.f;

        #pragma unroll 1
        for (int kt = 0; kt < 16; kt++) {
            float af[4];
            af[0] = smem[(m0 + g) * 132 + kt * 8 + t4];
            af[1] = smem[(m0 + g + 8) * 132 + kt * 8 + t4];
            af[2] = smem[(m0 + g) * 132 + kt * 8 + t4 + 4];
            af[3] = smem[(m0 + g + 8) * 132 + kt * 8 + t4 + 4];
            uint32_t ahi[4], alo[4];
            #pragma unroll
            for (int j = 0; j < 4; j++) {
                ahi[j] = f2tf32(af[j]);
                alo[j] = f2tf32(af[j] - __uint_as_float(ahi[j]));
            }
            const float4* bf = &g_WcFrag[(kt * 64 + grp * 16) * 32 + lane];
            #pragma unroll
            for (int nt = 0; nt < 16; nt++) {
                float4 f = bf[nt * 32];
                uint32_t bh0 = __float_as_uint(f.x), bh1 = __float_as_uint(f.y);
                uint32_t bl0 = __float_as_uint(f.z), bl1 = __float_as_uint(f.w);
                mma_tf32(c[nt], ahi, bh0, bh1);
                mma_tf32(c[nt], alo, bh0, bh1);
                mma_tf32(c[nt], ahi, bl0, bl1);
            }
        }

        float* C = (grp == 0) ? g_acc : (grp == 1) ? g_Q : (grp == 2) ? g_Kf : g_V;
        int colBase = grp * 128;
        #pragma unroll
        for (int nt = 0; nt < 16; nt++) {
            int col = nt * 8 + t4 * 2;
            float2 b = *reinterpret_cast<const float2*>(&g_bc[colBase + col]);
            if (r0 < M)
                *reinterpret_cast<float2*>(&C[r0 * 128 + col]) =
                    make_float2(c[nt][0] + b.x, c[nt][1] + b.y);
            if (r1 < M)
                *reinterpret_cast<float2*>(&C[r1 * 128 + col]) =
                    make_float2(c[nt][2] + b.x, c[nt][3] + b.y);
        }
    }
}

// ---------------- fused edge kernel (R7/R12/R14: tf32 mma, C staging, shfl epilogue) ----------------
// per block: 128 edges, 256 threads. Warp w: rows w*16, all 128 cols (c[16][4]).
// smem (floats): [0,16896) C stage [128][132] (EF raw [128][68] first)
//                [16896,17920) A2; [17920,17928) b2
#define ESM_A2  16896
#define ESM_B2  17920
#define ESM_FLOATS 17928
#define ESM_BYTES (ESM_FLOATS * 4)

__global__ void __launch_bounds__(256) edge_fused_kernel(
    const float* __restrict__ EF, const int* __restrict__ EI, int E,
    const float* __restrict__ A2, const float* __restrict__ b2) {
    extern __shared__ float smem[];

    int tid = threadIdx.x;
    int e0 = blockIdx.x * 128;

    for (int i = tid; i < 1024; i += 256) smem[ESM_A2 + i] = A2[i];
    if (tid < 8) smem[ESM_B2 + tid] = b2[tid];

    // stage EF raw: 128 rows x 64 feats, stride 68 (2048 float4, 8/thread)
    #pragma unroll
    for (int i = 0; i < 8; i++) {
        int s = tid + i * 256;
        int r = s >> 4, c4 = s & 15;
        int e = e0 + r;
        float4 v = make_float4(0.f, 0.f, 0.f, 0.f);
        if (e < E) v = *reinterpret_cast<const float4*>(&EF[e * 64 + c4 * 4]);
        *reinterpret_cast<float4*>(&smem[r * 68 + c4 * 4]) = v;
    }
    __syncthreads();

    int w = tid >> 5, lane = tid & 31;
    int g = lane >> 2, t4 = lane & 3;
    int m0 = w * 16;

    float c[16][4];
    #pragma unroll
    for (int nt = 0; nt < 16; nt++)
        #pragma unroll
        for (int j = 0; j < 4; j++) c[nt][j] = 0.f;

    #pragma unroll 1
    for (int kt = 0; kt < 8; kt++) {
        float af[4];
        af[0] = smem[(m0 + g) * 68 + kt * 8 + t4];
        af[1] = smem[(m0 + g + 8) * 68 + kt * 8 + t4];
        af[2] = smem[(m0 + g) * 68 + kt * 8 + t4 + 4];
        af[3] = smem[(m0 + g + 8) * 68 + kt * 8 + t4 + 4];
        uint32_t ahi[4], alo[4];
        #pragma unroll
        for (int j = 0; j < 4; j++) {
            ahi[j] = f2tf32(af[j]);
            alo[j] = f2tf32(af[j] - __uint_as_float(ahi[j]));
        }
        const float4* bf = &g_MeFrag[(kt * 16) * 32 + lane];
        #pragma unroll
        for (int nt = 0; nt < 16; nt++) {
            float4 f = bf[nt * 32];
            uint32_t bh0 = __float_as_uint(f.x), bh1 = __float_as_uint(f.y);
            uint32_t bl0 = __float_as_uint(f.z), bl1 = __float_as_uint(f.w);
            mma_tf32(c[nt], ahi, bh0, bh1);
            mma_tf32(c[nt], alo, bh0, bh1);
            mma_tf32(c[nt], ahi, bl0, bl1);
        }
    }
    __syncthreads();   // all EF reads done before C overwrites the region

    // stage C: [edge][col], stride 132
    #pragma unroll
    for (int nt = 0; nt < 16; nt++) {
        int col = nt * 8 + t4 * 2;
        *reinterpret_cast<float2*>(&smem[(m0 + g) * 132 + col]) =
            make_float2(c[nt][0], c[nt][1]);
        *reinterpret_cast<float2*>(&smem[(m0 + g + 8) * 132 + col]) =
            make_float2(c[nt][2], c[nt][3]);
    }
    __syncthreads();

    // epilogue: gather Xq/Xk, lrelu, A2 heads, shfl reduce
    int tx = tid & 15, ty = tid >> 4;
    float4 c10 = *reinterpret_cast<const float4*>(&g_c1[tx * 4]);
    float4 c11 = *reinterpret_cast<const float4*>(&g_c1[64 + tx * 4]);

    float p[8][8];
    #pragma unroll
    for (int i = 0; i < 8; i++) {
        int el = ty * 8 + i;
        int e = e0 + el;
        int ec = (e < E) ? e : (E - 1);
        int src = EI[ec], tgt = EI[E + ec];
        float4 a0 = *reinterpret_cast<const float4*>(&smem[el * 132 + tx * 4]);
        float4 a1 = *reinterpret_cast<const float4*>(&smem[el * 132 + 64 + tx * 4]);
        float4 q0 = *reinterpret_cast<const float4*>(&g_Q[src * 128 + tx * 4]);
        float4 q1 = *reinterpret_cast<const float4*>(&g_Q[src * 128 + 64 + tx * 4]);
        float4 k0v = *reinterpret_cast<const float4*>(&g_Kf[tgt * 128 + tx * 4]);
        float4 k1v = *reinterpret_cast<const float4*>(&g_Kf[tgt * 128 + 64 + tx * 4]);
        float hm[8];
        hm[0] = lrelu(a0.x + q0.x + k0v.x + c10.x);
        hm[1] = lrelu(a0.y + q0.y + k0v.y + c10.y);
        hm[2] = lrelu(a0.z + q0.z + k0v.z + c10.z);
        hm[3] = lrelu(a0.w + q0.w + k0v.w + c10.w);
        hm[4] = lrelu(a1.x + q1.x + k1v.x + c11.x);
        hm[5] = lrelu(a1.y + q1.y + k1v.y + c11.y);
        hm[6] = lrelu(a1.z + q1.z + k1v.z + c11.z);
        hm[7] = lrelu(a1.w + q1.w + k1v.w + c11.w);
        #pragma unroll
        for (int h = 0; h < 8; h++) {
            float s = 0.f;
            #pragma unroll
            for (int jj = 0; jj < 4; jj++) {
                s += hm[jj]     * smem[ESM_A2 + (tx * 4 + jj) * 8 + h];
                s += hm[4 + jj] * smem[ESM_A2 + (64 + tx * 4 + jj) * 8 + h];
            }
            p[i][h] = s;
        }
    }
    #pragma unroll
    for (int off = 1; off < 16; off <<= 1) {
        #pragma unroll
        for (int i = 0; i < 8; i++)
            #pragma unroll
            for (int h = 0; h < 8; h++)
                p[i][h] += __shfl_xor_sync(0xffffffffu, p[i][h], off);
    }
    if (tx == 0) {
        #pragma unroll
        for (int i = 0; i < 8; i++) {
            int e = e0 + ty * 8 + i;
            if (e < E) {
                float ssum = 0.f;
                #pragma unroll
                for (int h = 0; h < 8; h++) ssum += lrelu(p[i][h] + smem[ESM_B2 + h]);
                g_s[e] = ssum * 0.125f;
            }
        }
    }
}

// ---------------- global softmax over E edges: one pass + combine ----------------
__global__ void __launch_bounds__(256) softmax_part_kernel(int E) {
    float m = -3.4e38f, sum = 0.f;
    for (int i = blockIdx.x * 256 + threadIdx.x; i < E; i += gridDim.x * 256) {
        float v = g_s[i];
        if (v > m) { sum = sum * __expf(m - v) + 1.f; m = v; }
        else       { sum += __expf(v - m); }
    }
    __shared__ float sm[256], su[256];
    sm[threadIdx.x] = m; su[threadIdx.x] = sum;
    __syncthreads();
    for (int off = 128; off; off >>= 1) {
        if (threadIdx.x < off) {
            float m2 = sm[threadIdx.x + off], s2 = su[threadIdx.x + off];
            float mm = fmaxf(sm[threadIdx.x], m2);
            su[threadIdx.x] = su[threadIdx.x] * __expf(sm[threadIdx.x] - mm) + s2 * __expf(m2 - mm);
            sm[threadIdx.x] = mm;
        }
        __syncthreads();
    }
    if (threadIdx.x == 0) { g_pmax[blockIdx.x] = sm[0]; g_psum[blockIdx.x] = su[0]; }
}

__global__ void __launch_bounds__(512) softmax_final_kernel() {
    __shared__ float sm[512], su[512];
    int t = threadIdx.x;
    sm[t] = g_pmax[t]; su[t] = g_psum[t];
    __syncthreads();
    for (int off = 256; off; off >>= 1) {
        if (t < off) {
            float m2 = sm[t + off], s2 = su[t + off];
            float mm = fmaxf(sm[t], m2);
            su[t] = su[t] * __expf(sm[t] - mm) + s2 * __expf(m2 - mm);
            sm[t] = mm;
        }
        __syncthreads();
    }
    if (t == 0) { g_red[0] = sm[0]; g_red[1] = 1.0f / su[0]; }
}

// ---------------- scatter: acc[src] += w[e] * v[tgt] ----------------
__global__ void __launch_bounds__(256) scatter_kernel(const int* __restrict__ EI, int E) {
    int t = blockIdx.x * 256 + threadIdx.x;
    int e = t >> 5;
    if (e >= E) return;
    int lane = t & 31;
    float gmax = g_red[0], ginv = g_red[1];
    float w = __expf(g_s[e] - gmax) * ginv;
    int src = EI[e], tgt = EI[E + e];
    float4 v = *reinterpret_cast<const float4*>(&g_V[tgt * 128 + lane * 4]);
    float* dst = &g_acc[src * 128 + lane * 4];
    asm volatile("red.global.add.v4.f32 [%0], {%1, %2, %3, %4};"
                 :: "l"(dst), "f"(w * v.x), "f"(w * v.y), "f"(w * v.z), "f"(w * v.w)
                 : "memory");
}

// ---------------- layernorm epilogue (reads g_acc = H + scatter) ----------------
__global__ void __launch_bounds__(256) ln_kernel(const float* __restrict__ gamma,
                                                 const float* __restrict__ beta,
                                                 float* __restrict__ out, int Nn) {
    int warp = threadIdx.x >> 5, lane = threadIdx.x & 31;
    int n = blockIdx.x * 8 + warp;
    if (n >= Nn) return;
    float4 a = *reinterpret_cast<const float4*>(&g_acc[n * 128 + lane * 4]);
    float y[4] = {a.x, a.y, a.z, a.w};
    float sum = y[0] + y[1] + y[2] + y[3];
    float sq  = y[0] * y[0] + y[1] * y[1] + y[2] * y[2] + y[3] * y[3];
    #pragma unroll
    for (int off = 16; off >= 1; off >>= 1) {
        sum += __shfl_xor_sync(0xffffffffu, sum, off);
        sq  += __shfl_xor_sync(0xffffffffu, sq, off);
    }
    float mu  = sum * (1.f / 128.f);
    float var = sq * (1.f / 128.f) - mu * mu;
    float rs = rsqrtf(var + 1e-5f);
    #pragma unroll
    for (int c = 0; c < 4; c++) {
        int j = lane * 4 + c;
        out[n * 128 + j] = gamma[j] * (y[c] - mu) * rs + beta[j];
    }
}

// ---------------- launch ----------------
extern "C" void kernel_launch(void* const* d_in, const int* in_sizes, int n_in,
                              void* d_out, int out_size) {
    const float* node_features = (const float*)d_in[0];
    const float* edge_features = (const float*)d_in[1];
    const float* Wn = (const float*)d_in[2];
    const float* bn = (const float*)d_in[3];
    const float* Wq = (const float*)d_in[4];
    const float* bq = (const float*)d_in[5];
    const float* Wk = (const float*)d_in[6];
    const float* bk = (const float*)d_in[7];
    const float* Wv = (const float*)d_in[8];
    const float* bv = (const float*)d_in[9];
    const float* We = (const float*)d_in[10];
    const float* be = (const float*)d_in[11];
    const float* A1 = (const float*)d_in[12];
    const float* b1 = (const float*)d_in[13];
    const float* A2 = (const float*)d_in[14];
    const float* b2 = (const float*)d_in[15];
    const float* gamma = (const float*)d_in[16];
    const float* beta  = (const float*)d_in[17];
    const int*   EI    = (const int*)d_in[18];
    float* out = (float*)d_out;

    int Nn = in_sizes[0] / 128;
    int E  = in_sizes[18] / 2;

    cudaFuncSetAttribute(edge_fused_kernel,
                         cudaFuncAttributeMaxDynamicSharedMemorySize, ESM_BYTES);
    cudaFuncSetAttribute(node_gemm_kernel,
                         cudaFuncAttributeMaxDynamicSharedMemorySize, NSM_BYTES);

    prep_kernel<<<(4096 + 32768 + 128 + 512 + 255) / 256, 256>>>(
        Wn, Wq, Wk, Wv, We, A1, b1, bq, bk, be, bn, bv);
    node_gemm_kernel<<<(Nn + 127) / 128, 256, NSM_BYTES>>>(node_features, Nn);
    edge_fused_kernel<<<(E + 127) / 128, 256, ESM_BYTES>>>(edge_features, EI, E, A2, b2);
    softmax_part_kernel<<<512, 256>>>(E);
    softmax_final_kernel<<<1, 512>>>();
    scatter_kernel<<<(E * 32 + 255) / 256, 256>>>(EI, E);
    ln_kernel<<<(Nn + 7) / 8, 256>>>(gamma, beta, out, Nn);
}

// round 17
// speedup vs baseline: 1.1767x; 1.1767x over previous
#include <cuda_runtime.h>
#include <cstdint>

#define NN_MAX 50000
#define EE_MAX 400000

// ---------------- scratch (device globals; no allocs allowed) ----------------
__device__ float g_bc[512];                   // bn | 0 | 0 | bv
__device__ float4 g_MeFrag[8 * 16 * 32];      // Me fragments (hi0,hi1,lo0,lo1)
__device__ float4 g_WcFrag[16 * 64 * 32];     // Wcomb fragments (hi0,hi1,lo0,lo1), 512KB
__device__ float g_c1[128];                   // bq@A1q + bk@A1k + be@A1e + b1
__device__ float g_Q[NN_MAX * 128];
__device__ float g_Kf[NN_MAX * 128];
__device__ float g_V[NN_MAX * 128];
__device__ float g_s[EE_MAX];
__device__ float g_pmax[512];
__device__ float g_psum[512];
__device__ float g_red[2];                    // gmax, 1/gsum
__device__ float g_acc[NN_MAX * 128];         // H written by node_gemm; scatter adds; ln reads

__device__ __forceinline__ float lrelu(float x) { return x > 0.f ? x : 0.2f * x; }

__device__ __forceinline__ uint32_t f2tf32(float x) {
    uint32_t r; asm("cvt.rna.tf32.f32 %0, %1;" : "=r"(r) : "f"(x)); return r;
}

__device__ __forceinline__ void mma_tf32(float c[4], const uint32_t a[4],
                                         uint32_t b0, uint32_t b1) {
    asm volatile(
        "mma.sync.aligned.m16n8k8.row.col.f32.tf32.tf32.f32 "
        "{%0,%1,%2,%3}, {%4,%5,%6,%7}, {%8,%9}, {%0,%1,%2,%3};"
        : "+f"(c[0]), "+f"(c[1]), "+f"(c[2]), "+f"(c[3])
        : "r"(a[0]), "r"(a[1]), "r"(a[2]), "r"(a[3]), "r"(b0), "r"(b1));
}

// ---------------- prep: fold weights into fragment layouts ----------------
__global__ void prep_kernel(const float* __restrict__ Wn, const float* __restrict__ Wq,
                            const float* __restrict__ Wk, const float* __restrict__ Wv,
                            const float* __restrict__ We, const float* __restrict__ A1,
                            const float* __restrict__ b1, const float* __restrict__ bq,
                            const float* __restrict__ bk, const float* __restrict__ be,
                            const float* __restrict__ bn, const float* __restrict__ bv) {
    int t = blockIdx.x * 256 + threadIdx.x;
    if (t < 4096) {
        int i = t;
        int kt = i >> 9, nt = (i >> 5) & 15, lane = i & 31;
        int g = lane >> 2, t4 = lane & 3;
        int k1 = kt * 8 + t4, k2 = k1 + 4;
        int n = nt * 8 + g;
        float s1 = 0.f, s2 = 0.f;
        #pragma unroll 8
        for (int u = 0; u < 128; u++) {
            float a = A1[(256 + u) * 128 + n];
            s1 += We[k1 * 128 + u] * a;
            s2 += We[k2 * 128 + u] * a;
        }
        float h1 = __uint_as_float(f2tf32(s1));
        float h2 = __uint_as_float(f2tf32(s2));
        float l1 = __uint_as_float(f2tf32(s1 - h1));
        float l2 = __uint_as_float(f2tf32(s2 - h2));
        g_MeFrag[i] = make_float4(h1, h2, l1, l2);
    } else if (t < 4096 + 32768) {
        int i = t - 4096;
        int kt = i >> 11, nt = (i >> 5) & 63, lane = i & 31;
        int g = lane >> 2, t4 = lane & 3;
        int k1 = kt * 8 + t4, k2 = k1 + 4;
        int n = nt * 8 + g;
        float s1, s2;
        if (n < 128) {
            s1 = Wn[k1 * 128 + n];
            s2 = Wn[k2 * 128 + n];
        } else if (n < 256) {
            int j = n - 128;
            s1 = 0.f; s2 = 0.f;
            #pragma unroll 8
            for (int u = 0; u < 128; u++) {
                float a = A1[u * 128 + j];
                s1 += Wq[k1 * 128 + u] * a;
                s2 += Wq[k2 * 128 + u] * a;
            }
        } else if (n < 384) {
            int j = n - 256;
            s1 = 0.f; s2 = 0.f;
            #pragma unroll 8
            for (int u = 0; u < 128; u++) {
                float a = A1[(128 + u) * 128 + j];
                s1 += Wk[k1 * 128 + u] * a;
                s2 += Wk[k2 * 128 + u] * a;
            }
        } else {
            int j = n - 384;
            s1 = Wv[k1 * 128 + j];
            s2 = Wv[k2 * 128 + j];
        }
        float h1 = __uint_as_float(f2tf32(s1));
        float h2 = __uint_as_float(f2tf32(s2));
        float l1 = __uint_as_float(f2tf32(s1 - h1));
        float l2 = __uint_as_float(f2tf32(s2 - h2));
        g_WcFrag[(kt * 64 + nt) * 32 + lane] = make_float4(h1, h2, l1, l2);
    } else if (t < 4096 + 32768 + 128) {
        int j = t - (4096 + 32768);
        float s = b1[j];
        for (int u = 0; u < 128; u++) {
            s += bq[u] * A1[u * 128 + j];
            s += bk[u] * A1[(128 + u) * 128 + j];
            s += be[u] * A1[(256 + u) * 128 + j];
        }
        g_c1[j] = s;
    } else if (t < 4096 + 32768 + 128 + 512) {
        int j = t - (4096 + 32768 + 128);
        g_bc[j] = (j < 128) ? bn[j] : (j >= 384 ? bv[j - 384] : 0.f);
    }
}

// ---------------- node GEMM (tf32 mma): C[M,512] = A @ Wcomb + bc ----------------
// grp 0 (H) goes directly into g_acc (scatter accumulates on top; ln reads g_acc).
#define NSM_FLOATS (128 * 132)
#define NSM_BYTES  (NSM_FLOATS * 4)

__global__ void __launch_bounds__(256) node_gemm_kernel(const float* __restrict__ A, int M) {
    extern __shared__ float smem[];
    int tid = threadIdx.x;
    int rowBase = blockIdx.y * 128;

    #pragma unroll
    for (int i = 0; i < 16; i++) {
        int s = tid + i * 256;
        int r = s >> 5, c4 = s & 31;
        int row = rowBase + r;
        float4 v = make_float4(0.f, 0.f, 0.f, 0.f);
        if (row < M) v = *reinterpret_cast<const float4*>(&A[row * 128 + c4 * 4]);
        *reinterpret_cast<float4*>(&smem[r * 132 + c4 * 4]) = v;
    }
    __syncthreads();

    int w = tid >> 5, lane = tid & 31;
    int g = lane >> 2, t4 = lane & 3;
    int m0 = w * 16;

    float c[16][4];
    #pragma unroll
    for (int nt = 0; nt < 16; nt++)
        #pragma unroll
        for (int j = 0; j < 4; j++) c[nt][j] = 0.f;

    #pragma unroll 1
    for (int kt = 0; kt < 16; kt++) {
        float af[4];
        af[0] = smem[(m0 + g) * 132 + kt * 8 + t4];
        af[1] = smem[(m0 + g + 8) * 132 + kt * 8 + t4];
        af[2] = smem[(m0 + g) * 132 + kt * 8 + t4 + 4];
        af[3] = smem[(m0 + g + 8) * 132 + kt * 8 + t4 + 4];
        uint32_t ahi[4], alo[4];
        #pragma unroll
        for (int j = 0; j < 4; j++) {
            ahi[j] = f2tf32(af[j]);
            alo[j] = f2tf32(af[j] - __uint_as_float(ahi[j]));
        }
        const float4* bf = &g_WcFrag[(kt * 64 + blockIdx.x * 16) * 32 + lane];
        #pragma unroll
        for (int nt = 0; nt < 16; nt++) {
            float4 f = bf[nt * 32];
            uint32_t bh0 = __float_as_uint(f.x), bh1 = __float_as_uint(f.y);
            uint32_t bl0 = __float_as_uint(f.z), bl1 = __float_as_uint(f.w);
            mma_tf32(c[nt], ahi, bh0, bh1);
            mma_tf32(c[nt], alo, bh0, bh1);
            mma_tf32(c[nt], ahi, bl0, bl1);
        }
    }

    int grp = blockIdx.x;
    float* C = (grp == 0) ? g_acc : (grp == 1) ? g_Q : (grp == 2) ? g_Kf : g_V;
    int colBase = grp * 128;
    int r0 = rowBase + m0 + g, r1 = r0 + 8;
    #pragma unroll
    for (int nt = 0; nt < 16; nt++) {
        int col = nt * 8 + t4 * 2;
        float2 b = *reinterpret_cast<const float2*>(&g_bc[colBase + col]);
        if (r0 < M)
            *reinterpret_cast<float2*>(&C[r0 * 128 + col]) =
                make_float2(c[nt][0] + b.x, c[nt][1] + b.y);
        if (r1 < M)
            *reinterpret_cast<float2*>(&C[r1 * 128 + col]) =
                make_float2(c[nt][2] + b.x, c[nt][3] + b.y);
    }
}

// ---------------- fused edge kernel (R14 + 2 blocks/SM via reg cap) ----------------
// per block: 128 edges, 256 threads. Warp w: rows w*16, all 128 cols (c[16][4]).
// __launch_bounds__(256,2): cap regs at 128 so TWO blocks co-reside per SM
// (smem 2x71.7KB fits); offset phases overlap gather with MMA across blocks.
// smem (floats): [0,16896) C stage [128][132] (EF raw [128][68] first)
//                [16896,17920) A2; [17920,17928) b2
#define ESM_A2  16896
#define ESM_B2  17920
#define ESM_FLOATS 17928
#define ESM_BYTES (ESM_FLOATS * 4)

__global__ void __launch_bounds__(256, 2) edge_fused_kernel(
    const float* __restrict__ EF, const int* __restrict__ EI, int E,
    const float* __restrict__ A2, const float* __restrict__ b2) {
    extern __shared__ float smem[];

    int tid = threadIdx.x;
    int e0 = blockIdx.x * 128;

    for (int i = tid; i < 1024; i += 256) smem[ESM_A2 + i] = A2[i];
    if (tid < 8) smem[ESM_B2 + tid] = b2[tid];

    // stage EF raw: 128 rows x 64 feats, stride 68 (2048 float4, 8/thread)
    #pragma unroll
    for (int i = 0; i < 8; i++) {
        int s = tid + i * 256;
        int r = s >> 4, c4 = s & 15;
        int e = e0 + r;
        float4 v = make_float4(0.f, 0.f, 0.f, 0.f);
        if (e < E) v = *reinterpret_cast<const float4*>(&EF[e * 64 + c4 * 4]);
        *reinterpret_cast<float4*>(&smem[r * 68 + c4 * 4]) = v;
    }
    __syncthreads();

    int w = tid >> 5, lane = tid & 31;
    int g = lane >> 2, t4 = lane & 3;
    int m0 = w * 16;

    float c[16][4];
    #pragma unroll
    for (int nt = 0; nt < 16; nt++)
        #pragma unroll
        for (int j = 0; j < 4; j++) c[nt][j] = 0.f;

    #pragma unroll 1
    for (int kt = 0; kt < 8; kt++) {
        float af[4];
        af[0] = smem[(m0 + g) * 68 + kt * 8 + t4];
        af[1] = smem[(m0 + g + 8) * 68 + kt * 8 + t4];
        af[2] = smem[(m0 + g) * 68 + kt * 8 + t4 + 4];
        af[3] = smem[(m0 + g + 8) * 68 + kt * 8 + t4 + 4];
        uint32_t ahi[4], alo[4];
        #pragma unroll
        for (int j = 0; j < 4; j++) {
            ahi[j] = f2tf32(af[j]);
            alo[j] = f2tf32(af[j] - __uint_as_float(ahi[j]));
        }
        const float4* bf = &g_MeFrag[(kt * 16) * 32 + lane];
        #pragma unroll
        for (int nt = 0; nt < 16; nt++) {
            float4 f = bf[nt * 32];
            uint32_t bh0 = __float_as_uint(f.x), bh1 = __float_as_uint(f.y);
            uint32_t bl0 = __float_as_uint(f.z), bl1 = __float_as_uint(f.w);
            mma_tf32(c[nt], ahi, bh0, bh1);
            mma_tf32(c[nt], alo, bh0, bh1);
            mma_tf32(c[nt], ahi, bl0, bl1);
        }
    }
    __syncthreads();   // all EF reads done before C overwrites the region

    // stage C: [edge][col], stride 132
    #pragma unroll
    for (int nt = 0; nt < 16; nt++) {
        int col = nt * 8 + t4 * 2;
        *reinterpret_cast<float2*>(&smem[(m0 + g) * 132 + col]) =
            make_float2(c[nt][0], c[nt][1]);
        *reinterpret_cast<float2*>(&smem[(m0 + g + 8) * 132 + col]) =
            make_float2(c[nt][2], c[nt][3]);
    }
    __syncthreads();

    // epilogue: gather Xq/Xk, lrelu, A2 heads, shfl reduce
    int tx = tid & 15, ty = tid >> 4;
    float4 c10 = *reinterpret_cast<const float4*>(&g_c1[tx * 4]);
    float4 c11 = *reinterpret_cast<const float4*>(&g_c1[64 + tx * 4]);

    float p[8][8];
    #pragma unroll
    for (int i = 0; i < 8; i++) {
        int el = ty * 8 + i;
        int e = e0 + el;
        int ec = (e < E) ? e : (E - 1);
        int src = EI[ec], tgt = EI[E + ec];
        float4 a0 = *reinterpret_cast<const float4*>(&smem[el * 132 + tx * 4]);
        float4 a1 = *reinterpret_cast<const float4*>(&smem[el * 132 + 64 + tx * 4]);
        float4 q0 = *reinterpret_cast<const float4*>(&g_Q[src * 128 + tx * 4]);
        float4 q1 = *reinterpret_cast<const float4*>(&g_Q[src * 128 + 64 + tx * 4]);
        float4 k0v = *reinterpret_cast<const float4*>(&g_Kf[tgt * 128 + tx * 4]);
        float4 k1v = *reinterpret_cast<const float4*>(&g_Kf[tgt * 128 + 64 + tx * 4]);
        float hm[8];
        hm[0] = lrelu(a0.x + q0.x + k0v.x + c10.x);
        hm[1] = lrelu(a0.y + q0.y + k0v.y + c10.y);
        hm[2] = lrelu(a0.z + q0.z + k0v.z + c10.z);
        hm[3] = lrelu(a0.w + q0.w + k0v.w + c10.w);
        hm[4] = lrelu(a1.x + q1.x + k1v.x + c11.x);
        hm[5] = lrelu(a1.y + q1.y + k1v.y + c11.y);
        hm[6] = lrelu(a1.z + q1.z + k1v.z + c11.z);
        hm[7] = lrelu(a1.w + q1.w + k1v.w + c11.w);
        #pragma unroll
        for (int h = 0; h < 8; h++) {
            float s = 0.f;
            #pragma unroll
            for (int jj = 0; jj < 4; jj++) {
                s += hm[jj]     * smem[ESM_A2 + (tx * 4 + jj) * 8 + h];
                s += hm[4 + jj] * smem[ESM_A2 + (64 + tx * 4 + jj) * 8 + h];
            }
            p[i][h] = s;
        }
    }
    #pragma unroll
    for (int off = 1; off < 16; off <<= 1) {
        #pragma unroll
        for (int i = 0; i < 8; i++)
            #pragma unroll
            for (int h = 0; h < 8; h++)
                p[i][h] += __shfl_xor_sync(0xffffffffu, p[i][h], off);
    }
    if (tx == 0) {
        #pragma unroll
        for (int i = 0; i < 8; i++) {
            int e = e0 + ty * 8 + i;
            if (e < E) {
                float ssum = 0.f;
                #pragma unroll
                for (int h = 0; h < 8; h++) ssum += lrelu(p[i][h] + smem[ESM_B2 + h]);
                g_s[e] = ssum * 0.125f;
            }
        }
    }
}

// ---------------- global softmax over E edges: one pass + combine ----------------
__global__ void __launch_bounds__(256) softmax_part_kernel(int E) {
    float m = -3.4e38f, sum = 0.f;
    for (int i = blockIdx.x * 256 + threadIdx.x; i < E; i += gridDim.x * 256) {
        float v = g_s[i];
        if (v > m) { sum = sum * __expf(m - v) + 1.f; m = v; }
        else       { sum += __expf(v - m); }
    }
    __shared__ float sm[256], su[256];
    sm[threadIdx.x] = m; su[threadIdx.x] = sum;
    __syncthreads();
    for (int off = 128; off; off >>= 1) {
        if (threadIdx.x < off) {
            float m2 = sm[threadIdx.x + off], s2 = su[threadIdx.x + off];
            float mm = fmaxf(sm[threadIdx.x], m2);
            su[threadIdx.x] = su[threadIdx.x] * __expf(sm[threadIdx.x] - mm) + s2 * __expf(m2 - mm);
            sm[threadIdx.x] = mm;
        }
        __syncthreads();
    }
    if (threadIdx.x == 0) { g_pmax[blockIdx.x] = sm[0]; g_psum[blockIdx.x] = su[0]; }
}

__global__ void __launch_bounds__(512) softmax_final_kernel() {
    __shared__ float sm[512], su[512];
    int t = threadIdx.x;
    sm[t] = g_pmax[t]; su[t] = g_psum[t];
    __syncthreads();
    for (int off = 256; off; off >>= 1) {
        if (t < off) {
            float m2 = sm[t + off], s2 = su[t + off];
            float mm = fmaxf(sm[t], m2);
            su[t] = su[t] * __expf(sm[t] - mm) + s2 * __expf(m2 - mm);
            sm[t] = mm;
        }
        __syncthreads();
    }
    if (t == 0) { g_red[0] = sm[0]; g_red[1] = 1.0f / su[0]; }
}

// ---------------- scatter: acc[src] += w[e] * v[tgt] ----------------
__global__ void __launch_bounds__(256) scatter_kernel(const int* __restrict__ EI, int E) {
    int t = blockIdx.x * 256 + threadIdx.x;
    int e = t >> 5;
    if (e >= E) return;
    int lane = t & 31;
    float gmax = g_red[0], ginv = g_red[1];
    float w = __expf(g_s[e] - gmax) * ginv;
    int src = EI[e], tgt = EI[E + e];
    float4 v = *reinterpret_cast<const float4*>(&g_V[tgt * 128 + lane * 4]);
    float* dst = &g_acc[src * 128 + lane * 4];
    asm volatile("red.global.add.v4.f32 [%0], {%1, %2, %3, %4};"
                 :: "l"(dst), "f"(w * v.x), "f"(w * v.y), "f"(w * v.z), "f"(w * v.w)
                 : "memory");
}

// ---------------- layernorm epilogue (reads g_acc = H + scatter) ----------------
__global__ void __launch_bounds__(256) ln_kernel(const float* __restrict__ gamma,
                                                 const float* __restrict__ beta,
                                                 float* __restrict__ out, int Nn) {
    int warp = threadIdx.x >> 5, lane = threadIdx.x & 31;
    int n = blockIdx.x * 8 + warp;
    if (n >= Nn) return;
    float4 a = *reinterpret_cast<const float4*>(&g_acc[n * 128 + lane * 4]);
    float y[4] = {a.x, a.y, a.z, a.w};
    float sum = y[0] + y[1] + y[2] + y[3];
    float sq  = y[0] * y[0] + y[1] * y[1] + y[2] * y[2] + y[3] * y[3];
    #pragma unroll
    for (int off = 16; off >= 1; off >>= 1) {
        sum += __shfl_xor_sync(0xffffffffu, sum, off);
        sq  += __shfl_xor_sync(0xffffffffu, sq, off);
    }
    float mu  = sum * (1.f / 128.f);
    float var = sq * (1.f / 128.f) - mu * mu;
    float rs = rsqrtf(var + 1e-5f);
    #pragma unroll
    for (int c = 0; c < 4; c++) {
        int j = lane * 4 + c;
        out[n * 128 + j] = gamma[j] * (y[c] - mu) * rs + beta[j];
    }
}

// ---------------- launch ----------------
extern "C" void kernel_launch(void* const* d_in, const int* in_sizes, int n_in,
                              void* d_out, int out_size) {
    const float* node_features = (const float*)d_in[0];
    const float* edge_features = (const float*)d_in[1];
    const float* Wn = (const float*)d_in[2];
    const float* bn = (const float*)d_in[3];
    const float* Wq = (const float*)d_in[4];
    const float* bq = (const float*)d_in[5];
    const float* Wk = (const float*)d_in[6];
    const float* bk = (const float*)d_in[7];
    const float* Wv = (const float*)d_in[8];
    const float* bv = (const float*)d_in[9];
    const float* We = (const float*)d_in[10];
    const float* be = (const float*)d_in[11];
    const float* A1 = (const float*)d_in[12];
    const float* b1 = (const float*)d_in[13];
    const float* A2 = (const float*)d_in[14];
    const float* b2 = (const float*)d_in[15];
    const float* gamma = (const float*)d_in[16];
    const float* beta  = (const float*)d_in[17];
    const int*   EI    = (const int*)d_in[18];
    float* out = (float*)d_out;

    int Nn = in_sizes[0] / 128;
    int E  = in_sizes[18] / 2;

    cudaFuncSetAttribute(edge_fused_kernel,
                         cudaFuncAttributeMaxDynamicSharedMemorySize, ESM_BYTES);
    cudaFuncSetAttribute(node_gemm_kernel,
                         cudaFuncAttributeMaxDynamicSharedMemorySize, NSM_BYTES);

    prep_kernel<<<(4096 + 32768 + 128 + 512 + 255) / 256, 256>>>(
        Wn, Wq, Wk, Wv, We, A1, b1, bq, bk, be, bn, bv);
    node_gemm_kernel<<<dim3(4, (Nn + 127) / 128), 256, NSM_BYTES>>>(node_features, Nn);
    edge_fused_kernel<<<(E + 127) / 128, 256, ESM_BYTES>>>(edge_features, EI, E, A2, b2);
    softmax_part_kernel<<<512, 256>>>(E);
    softmax_final_kernel<<<1, 512>>>();
    scatter_kernel<<<(E * 32 + 255) / 256, 256>>>(EI, E);
    ln_kernel<<<(Nn + 7) / 8, 256>>>(gamma, beta, out, Nn);
}